// round 1
// baseline (speedup 1.0000x reference)
#include <cuda_runtime.h>
#include <math.h>

#define Bb     32
#define NPAIR  674
#define DPAIR  1636
#define DIN    768
#define DHID   512
#define DOUT   256
#define MROWS  21568   // Bb * NPAIR

// ---- scratch (static device globals: no allocation allowed) ----
__device__ float g_Wc[DPAIR * DHID];   // Wi @ W1[8]            (~3.3 MB)
__device__ float g_bc[DHID];           // bi @ W1[8] + b1[8]
__device__ float g_g2[Bb * DHID];      // (ac*674^-1/2) @ W1[2] + b1[2]
__device__ float g_Wd[DHID * DOUT];    // W2[8] @ Wo1
__device__ float g_bd[DOUT];           // b2[8] @ Wo1 + bo1
__device__ float g_hp[(size_t)MROWS * DHID];  // h_p  (~44 MB)

// ============================================================================
// Generic 128x128x8 SGEMM, 256 threads, 8x8 microtile.
// EPI=0: C = A@B (plain). EPI=1: C = relu((A@B + g_bc[n] + g_g2[row/674][n])*0.5)
// A row-major [M,K], B row-major [K,N]. Requires N%128==0, K%4==0.
// ============================================================================
template<int EPI>
__global__ __launch_bounds__(256) void sgemm128(
    const float* __restrict__ A, const float* __restrict__ Bm,
    float* __restrict__ C, int M, int N, int K)
{
    __shared__ float As[8][128];
    __shared__ float Bs[8][128];
    const int tid   = threadIdx.x;
    const int m0    = blockIdx.y * 128;
    const int n0    = blockIdx.x * 128;
    const int arow  = tid >> 1;          // 0..127
    const int acol4 = (tid & 1) * 4;     // 0 or 4
    const int brow  = tid >> 5;          // 0..7
    const int bcol4 = (tid & 31) * 4;    // 0..124
    const int tx    = tid & 15;
    const int ty    = tid >> 4;

    float acc[8][8];
    #pragma unroll
    for (int i = 0; i < 8; i++)
        #pragma unroll
        for (int j = 0; j < 8; j++) acc[i][j] = 0.f;

    for (int k0 = 0; k0 < K; k0 += 8) {
        float4 av = make_float4(0.f, 0.f, 0.f, 0.f);
        const int gr = m0 + arow;
        if (gr < M && (k0 + acol4) < K)   // K tail is multiple of 4 -> vector guard ok
            av = *(const float4*)(A + (size_t)gr * K + k0 + acol4);
        As[acol4 + 0][arow] = av.x;
        As[acol4 + 1][arow] = av.y;
        As[acol4 + 2][arow] = av.z;
        As[acol4 + 3][arow] = av.w;

        float4 bv = make_float4(0.f, 0.f, 0.f, 0.f);
        if ((k0 + brow) < K)
            bv = *(const float4*)(Bm + (size_t)(k0 + brow) * N + n0 + bcol4);
        *(float4*)&Bs[brow][bcol4] = bv;
        __syncthreads();

        #pragma unroll
        for (int kk = 0; kk < 8; kk++) {
            float a[8], b[8];
            *(float4*)&a[0] = *(const float4*)&As[kk][ty * 8];
            *(float4*)&a[4] = *(const float4*)&As[kk][ty * 8 + 4];
            *(float4*)&b[0] = *(const float4*)&Bs[kk][tx * 8];
            *(float4*)&b[4] = *(const float4*)&Bs[kk][tx * 8 + 4];
            #pragma unroll
            for (int i = 0; i < 8; i++)
                #pragma unroll
                for (int j = 0; j < 8; j++)
                    acc[i][j] = fmaf(a[i], b[j], acc[i][j]);
        }
        __syncthreads();
    }

    #pragma unroll
    for (int i = 0; i < 8; i++) {
        const int gr = m0 + ty * 8 + i;
        if (gr >= M) continue;
        if (EPI == 0) {
            #pragma unroll
            for (int j = 0; j < 8; j += 4) {
                const int c = n0 + tx * 8 + j;
                float4 v = make_float4(acc[i][j], acc[i][j + 1], acc[i][j + 2], acc[i][j + 3]);
                *(float4*)(C + (size_t)gr * N + c) = v;
            }
        } else {
            const int b = gr / NPAIR;
            const float* g2r = g_g2 + b * DHID;
            #pragma unroll
            for (int j = 0; j < 8; j += 4) {
                const int c = n0 + tx * 8 + j;
                float4 v;
                v.x = fmaxf((acc[i][j + 0] + g_bc[c + 0] + g2r[c + 0]) * 0.5f, 0.f);
                v.y = fmaxf((acc[i][j + 1] + g_bc[c + 1] + g2r[c + 1]) * 0.5f, 0.f);
                v.z = fmaxf((acc[i][j + 2] + g_bc[c + 2] + g2r[c + 2]) * 0.5f, 0.f);
                v.w = fmaxf((acc[i][j + 3] + g_bc[c + 3] + g2r[c + 3]) * 0.5f, 0.f);
                *(float4*)(C + (size_t)gr * N + c) = v;
            }
        }
    }
}

// ============================================================================
// Fused tail: hid = relu(h_p @ Wd + bd)  [64 rows x 256 cols per block, K=512],
// then out[row] = dot(hid_row, Wo2) + bo2 via warp reduction (hid never hits gmem).
// ============================================================================
__global__ __launch_bounds__(256) void tail_kernel(
    const float* __restrict__ Wo2, const float* __restrict__ bo2,
    float* __restrict__ out)
{
    __shared__ float As[16][64];
    __shared__ float Bs[16][256];
    const int tid  = threadIdx.x;
    const int m0   = blockIdx.x * 64;    // MROWS % 64 == 0
    const int lane = tid & 31;
    const int w    = tid >> 5;           // warp 0..7 -> rows w*8..w*8+7

    float acc[8][8];
    #pragma unroll
    for (int i = 0; i < 8; i++)
        #pragma unroll
        for (int j = 0; j < 8; j++) acc[i][j] = 0.f;

    const int arow = tid >> 2;           // 0..63
    const int akq  = (tid & 3) * 4;      // 0,4,8,12

    for (int k0 = 0; k0 < DHID; k0 += 16) {
        float4 av = *(const float4*)(g_hp + (size_t)(m0 + arow) * DHID + k0 + akq);
        As[akq + 0][arow] = av.x;
        As[akq + 1][arow] = av.y;
        As[akq + 2][arow] = av.z;
        As[akq + 3][arow] = av.w;
        #pragma unroll
        for (int r = 0; r < 4; r++) {
            const int lin  = tid + 256 * r;   // 0..1023
            const int krow = lin >> 6;        // 0..15
            const int c4   = (lin & 63) * 4;  // 0..252
            *(float4*)&Bs[krow][c4] =
                *(const float4*)(g_Wd + (size_t)(k0 + krow) * DOUT + c4);
        }
        __syncthreads();

        #pragma unroll
        for (int kk = 0; kk < 16; kk++) {
            float a[8], b[8];
            *(float4*)&a[0] = *(const float4*)&As[kk][w * 8];
            *(float4*)&a[4] = *(const float4*)&As[kk][w * 8 + 4];
            *(float4*)&b[0] = *(const float4*)&Bs[kk][lane * 8];
            *(float4*)&b[4] = *(const float4*)&Bs[kk][lane * 8 + 4];
            #pragma unroll
            for (int i = 0; i < 8; i++)
                #pragma unroll
                for (int j = 0; j < 8; j++)
                    acc[i][j] = fmaf(a[i], b[j], acc[i][j]);
        }
        __syncthreads();
    }

    float wo2[8];
    #pragma unroll
    for (int j = 0; j < 8; j++) wo2[j] = Wo2[lane * 8 + j];
    const float bo2v = bo2[0];

    #pragma unroll
    for (int i = 0; i < 8; i++) {
        float p = 0.f;
        #pragma unroll
        for (int j = 0; j < 8; j++) {
            const float h = fmaxf(acc[i][j] + g_bd[lane * 8 + j], 0.f);
            p = fmaf(h, wo2[j], p);
        }
        #pragma unroll
        for (int off = 16; off > 0; off >>= 1)
            p += __shfl_down_sync(0xffffffffu, p, off);
        if (lane == 0)
            out[m0 + w * 8 + i] = p + bo2v;
    }
}

// ============================================================================
// Small precompute kernels
// ============================================================================
__global__ void bc_kernel(const float* __restrict__ bi, const float* __restrict__ W18,
                          const float* __restrict__ b18)
{
    const int n = blockIdx.x * blockDim.x + threadIdx.x;   // 0..511
    float s = 0.f;
    for (int k = 0; k < DIN; k++) s = fmaf(bi[k], W18[(size_t)k * DHID + n], s);
    g_bc[n] = s + b18[n];
}

__global__ void g2_kernel(const float* __restrict__ ac, const float* __restrict__ W12,
                          const float* __restrict__ b12)
{
    const int b = blockIdx.x;       // 0..31
    const int n = threadIdx.x;      // 0..511
    const float scale = rsqrtf((float)NPAIR);
    float s = 0.f;
    const float* arow = ac + (size_t)b * DIN;
    for (int k = 0; k < DIN; k++) s = fmaf(arow[k], W12[(size_t)k * DHID + n], s);
    g_g2[b * DHID + n] = s * scale + b12[n];
}

__global__ void wd_kernel(const float* __restrict__ W28, const float* __restrict__ Wo1)
{
    const int m = blockIdx.x;       // 0..511
    const int n = threadIdx.x;      // 0..255
    float s = 0.f;
    const float* wrow = W28 + (size_t)m * DOUT;
    for (int k = 0; k < DOUT; k++) s = fmaf(wrow[k], Wo1[(size_t)k * DOUT + n], s);
    g_Wd[m * DOUT + n] = s;
}

__global__ void bd_kernel(const float* __restrict__ b28, const float* __restrict__ Wo1,
                          const float* __restrict__ bo1)
{
    const int n = threadIdx.x;      // 0..255
    float s = 0.f;
    for (int k = 0; k < DOUT; k++) s = fmaf(b28[k], Wo1[(size_t)k * DOUT + n], s);
    g_bd[n] = s + bo1[n];
}

// ============================================================================
// Launch. Live inputs only: cpe(0), ac(3), Wi(4), bi(5), W1(6), b1(7),
// W2(8), b2(9), Wo1(10), bo1(11), Wo2(12), bo2(13). he/hc are dead code.
// ============================================================================
extern "C" void kernel_launch(void* const* d_in, const int* in_sizes, int n_in,
                              void* d_out, int out_size)
{
    const float* cpe = (const float*)d_in[0];
    const float* ac  = (const float*)d_in[3];
    const float* Wi  = (const float*)d_in[4];
    const float* bi  = (const float*)d_in[5];
    const float* W1  = (const float*)d_in[6];
    const float* b1  = (const float*)d_in[7];
    const float* W2  = (const float*)d_in[8];
    const float* b2  = (const float*)d_in[9];
    const float* Wo1 = (const float*)d_in[10];
    const float* bo1 = (const float*)d_in[11];
    const float* Wo2 = (const float*)d_in[12];
    const float* bo2 = (const float*)d_in[13];
    float* out = (float*)d_out;

    float *pWc, *pHp;
    cudaGetSymbolAddress((void**)&pWc, g_Wc);
    cudaGetSymbolAddress((void**)&pHp, g_hp);

    const float* W18 = W1 + (size_t)8 * DIN * DHID;
    const float* b18 = b1 + 8 * DHID;
    const float* W12 = W1 + (size_t)2 * DIN * DHID;
    const float* b12 = b1 + 2 * DHID;
    const float* W28 = W2 + (size_t)8 * DHID * DOUT;
    const float* b28 = b2 + 8 * DOUT;

    // 1. Precompute folded weights/biases (independent, small).
    sgemm128<0><<<dim3(DHID / 128, (DPAIR + 127) / 128), 256>>>(
        Wi, W18, pWc, DPAIR, DHID, DIN);
    bc_kernel<<<2, 256>>>(bi, W18, b18);
    g2_kernel<<<Bb, DHID>>>(ac, W12, b12);
    wd_kernel<<<DHID, DOUT>>>(W28, Wo1);
    bd_kernel<<<1, DOUT>>>(b28, Wo1, bo1);

    // 2. Main GEMM + fused h_p epilogue: [21568,1636] @ [1636,512].
    sgemm128<1><<<dim3(DHID / 128, (MROWS + 127) / 128), 256>>>(
        cpe, pWc, pHp, MROWS, DHID, DPAIR);

    // 3. Fused second GEMM + ReLU + final Wo2 dot -> out [32*674].
    tail_kernel<<<MROWS / 64, 256>>>(Wo2, bo2, out);
}

// round 2
// speedup vs baseline: 1.8751x; 1.8751x over previous
#include <cuda_runtime.h>
#include <math.h>
#include <stdint.h>

#define Bb     32
#define NPAIR  674
#define DPAIR  1636
#define DIN    768
#define DHID   512
#define DOUT   256
#define MROWS  21568   // Bb * NPAIR

// ---- scratch (static device globals: no allocation allowed) ----
__device__ float g_Wc[DPAIR * DHID];          // Wi @ W1[8]
__device__ float g_bc[DHID];                  // bi @ W1[8] + b1[8]
__device__ float g_g2[Bb * DHID];             // (ac*674^-1/2) @ W1[2] + b1[2]
__device__ float g_Wd[DHID * DOUT];           // W2[8] @ Wo1
__device__ float g_bd[DOUT];                  // b2[8] @ Wo1 + bo1
__device__ float g_hp[(size_t)MROWS * DHID];  // h_p (~44 MB)

__device__ __forceinline__ uint32_t f2tf32(float f) {
    uint32_t u;
    asm("cvt.rna.tf32.f32 %0, %1;" : "=r"(u) : "f"(f));
    return u;
}

__device__ __forceinline__ void mma_tf32(float* d, const uint32_t* a, const uint32_t* b) {
    asm volatile(
        "mma.sync.aligned.m16n8k8.row.col.f32.tf32.tf32.f32 "
        "{%0,%1,%2,%3}, {%4,%5,%6,%7}, {%8,%9}, {%0,%1,%2,%3};"
        : "+f"(d[0]), "+f"(d[1]), "+f"(d[2]), "+f"(d[3])
        : "r"(a[0]), "r"(a[1]), "r"(a[2]), "r"(a[3]), "r"(b[0]), "r"(b[1]));
}

// ============================================================================
// TF32 tensor-core GEMM, 128x128 block tile, BK=16, 256 threads (8 warps 2x4),
// warp tile 64x32 via m16n8k8. Double-buffered smem, tf32-converted on store,
// k-major layout with stride 136 -> conflict-free fragment loads.
// EPI=0: C = A@B.  EPI=1: C = relu((A@B + g_bc[n] + g_g2[row/674][n]) * 0.5)
// A row-major [M,K], B row-major [K,N]. Requires N%128==0, K%4==0.
// ============================================================================
template<int EPI>
__global__ __launch_bounds__(256) void tf32gemm(
    const float* __restrict__ A, const float* __restrict__ Bm,
    float* __restrict__ C, int M, int N, int K)
{
    __shared__ uint32_t As[2][16][136];
    __shared__ uint32_t Bs[2][16][136];

    const int tid  = threadIdx.x;
    const int lane = tid & 31;
    const int wid  = tid >> 5;
    const int wm   = wid >> 2;          // 0..1
    const int wn   = wid & 3;           // 0..3
    const int m0   = blockIdx.y * 128;
    const int n0   = blockIdx.x * 128;

    // A loader: thread covers 8 consecutive k of one row
    const int ar  = tid >> 1;           // 0..127
    const int ah  = (tid & 1) * 8;      // 0 or 8
    // B loader: thread covers 8 consecutive n of one k-row
    const int bkr = tid >> 4;           // 0..15
    const int bc8 = (tid & 15) * 8;     // 0..120

    float acc[4][4][4];
    #pragma unroll
    for (int mt = 0; mt < 4; mt++)
        #pragma unroll
        for (int nt = 0; nt < 4; nt++)
            #pragma unroll
            for (int i = 0; i < 4; i++) acc[mt][nt][i] = 0.f;

    const int niter = (K + 15) >> 4;

    auto load_tile = [&](int buf, int k0) {
        float4 a1 = make_float4(0.f, 0.f, 0.f, 0.f), a2 = a1;
        const int gr = m0 + ar, kb = k0 + ah;
        if (gr < M && kb < K) {
            const float* p = A + (size_t)gr * K + kb;
            a1 = *(const float4*)p;
            if (kb + 4 < K) a2 = *(const float4*)(p + 4);
        }
        As[buf][ah + 0][ar] = f2tf32(a1.x);
        As[buf][ah + 1][ar] = f2tf32(a1.y);
        As[buf][ah + 2][ar] = f2tf32(a1.z);
        As[buf][ah + 3][ar] = f2tf32(a1.w);
        As[buf][ah + 4][ar] = f2tf32(a2.x);
        As[buf][ah + 5][ar] = f2tf32(a2.y);
        As[buf][ah + 6][ar] = f2tf32(a2.z);
        As[buf][ah + 7][ar] = f2tf32(a2.w);

        float4 b1 = make_float4(0.f, 0.f, 0.f, 0.f), b2 = b1;
        const int gk = k0 + bkr;
        if (gk < K) {
            const float* q = Bm + (size_t)gk * N + n0 + bc8;
            b1 = *(const float4*)q;
            b2 = *(const float4*)(q + 4);
        }
        Bs[buf][bkr][bc8 + 0] = f2tf32(b1.x);
        Bs[buf][bkr][bc8 + 1] = f2tf32(b1.y);
        Bs[buf][bkr][bc8 + 2] = f2tf32(b1.z);
        Bs[buf][bkr][bc8 + 3] = f2tf32(b1.w);
        Bs[buf][bkr][bc8 + 4] = f2tf32(b2.x);
        Bs[buf][bkr][bc8 + 5] = f2tf32(b2.y);
        Bs[buf][bkr][bc8 + 6] = f2tf32(b2.z);
        Bs[buf][bkr][bc8 + 7] = f2tf32(b2.w);
    };

    load_tile(0, 0);
    __syncthreads();

    for (int it = 0; it < niter; it++) {
        const int cur = it & 1;
        if (it + 1 < niter) load_tile(cur ^ 1, (it + 1) << 4);

        #pragma unroll
        for (int k8 = 0; k8 < 2; k8++) {
            const int kk = k8 * 8 + (lane & 3);
            const int mb = wm * 64 + (lane >> 2);
            const int nb = wn * 32 + (lane >> 2);
            uint32_t af[4][4], bf[4][2];
            #pragma unroll
            for (int mt = 0; mt < 4; mt++) {
                af[mt][0] = As[cur][kk    ][mb + mt * 16];
                af[mt][1] = As[cur][kk    ][mb + mt * 16 + 8];
                af[mt][2] = As[cur][kk + 4][mb + mt * 16];
                af[mt][3] = As[cur][kk + 4][mb + mt * 16 + 8];
            }
            #pragma unroll
            for (int nt = 0; nt < 4; nt++) {
                bf[nt][0] = Bs[cur][kk    ][nb + nt * 8];
                bf[nt][1] = Bs[cur][kk + 4][nb + nt * 8];
            }
            #pragma unroll
            for (int mt = 0; mt < 4; mt++)
                #pragma unroll
                for (int nt = 0; nt < 4; nt++)
                    mma_tf32(acc[mt][nt], af[mt], bf[nt]);
        }
        __syncthreads();
    }

    // Epilogue
    #pragma unroll
    for (int mt = 0; mt < 4; mt++) {
        #pragma unroll
        for (int half = 0; half < 2; half++) {
            const int r = m0 + wm * 64 + mt * 16 + (lane >> 2) + half * 8;
            if (r >= M) continue;
            const float* g2r = nullptr;
            if (EPI == 1) g2r = g_g2 + (r / NPAIR) * DHID;
            #pragma unroll
            for (int nt = 0; nt < 4; nt++) {
                const int c = n0 + wn * 32 + nt * 8 + 2 * (lane & 3);
                float v0 = acc[mt][nt][half * 2 + 0];
                float v1 = acc[mt][nt][half * 2 + 1];
                if (EPI == 1) {
                    v0 = fmaxf((v0 + g_bc[c    ] + g2r[c    ]) * 0.5f, 0.f);
                    v1 = fmaxf((v1 + g_bc[c + 1] + g2r[c + 1]) * 0.5f, 0.f);
                }
                *(float2*)(C + (size_t)r * N + c) = make_float2(v0, v1);
            }
        }
    }
}

// ============================================================================
// Fused tail (fp32, preserves precision): hid = relu(h_p @ Wd + bd), then
// out[row] = dot(hid_row, Wo2) + bo2 via warp reduction.
// ============================================================================
__global__ __launch_bounds__(256) void tail_kernel(
    const float* __restrict__ Wo2, const float* __restrict__ bo2,
    float* __restrict__ out)
{
    __shared__ float As[16][64];
    __shared__ float Bs[16][256];
    const int tid  = threadIdx.x;
    const int m0   = blockIdx.x * 64;
    const int lane = tid & 31;
    const int w    = tid >> 5;

    float acc[8][8];
    #pragma unroll
    for (int i = 0; i < 8; i++)
        #pragma unroll
        for (int j = 0; j < 8; j++) acc[i][j] = 0.f;

    const int arow = tid >> 2;
    const int akq  = (tid & 3) * 4;

    for (int k0 = 0; k0 < DHID; k0 += 16) {
        float4 av = *(const float4*)(g_hp + (size_t)(m0 + arow) * DHID + k0 + akq);
        As[akq + 0][arow] = av.x;
        As[akq + 1][arow] = av.y;
        As[akq + 2][arow] = av.z;
        As[akq + 3][arow] = av.w;
        #pragma unroll
        for (int r = 0; r < 4; r++) {
            const int lin  = tid + 256 * r;
            const int krow = lin >> 6;
            const int c4   = (lin & 63) * 4;
            *(float4*)&Bs[krow][c4] =
                *(const float4*)(g_Wd + (size_t)(k0 + krow) * DOUT + c4);
        }
        __syncthreads();

        #pragma unroll
        for (int kk = 0; kk < 16; kk++) {
            float a[8], b[8];
            *(float4*)&a[0] = *(const float4*)&As[kk][w * 8];
            *(float4*)&a[4] = *(const float4*)&As[kk][w * 8 + 4];
            *(float4*)&b[0] = *(const float4*)&Bs[kk][lane * 8];
            *(float4*)&b[4] = *(const float4*)&Bs[kk][lane * 8 + 4];
            #pragma unroll
            for (int i = 0; i < 8; i++)
                #pragma unroll
                for (int j = 0; j < 8; j++)
                    acc[i][j] = fmaf(a[i], b[j], acc[i][j]);
        }
        __syncthreads();
    }

    float wo2[8];
    #pragma unroll
    for (int j = 0; j < 8; j++) wo2[j] = Wo2[lane * 8 + j];
    const float bo2v = bo2[0];

    #pragma unroll
    for (int i = 0; i < 8; i++) {
        float p = 0.f;
        #pragma unroll
        for (int j = 0; j < 8; j++) {
            const float h = fmaxf(acc[i][j] + g_bd[lane * 8 + j], 0.f);
            p = fmaf(h, wo2[j], p);
        }
        #pragma unroll
        for (int off = 16; off > 0; off >>= 1)
            p += __shfl_down_sync(0xffffffffu, p, off);
        if (lane == 0)
            out[m0 + w * 8 + i] = p + bo2v;
    }
}

// ============================================================================
// Small precompute kernels
// ============================================================================
__global__ void bc_kernel(const float* __restrict__ bi, const float* __restrict__ W18,
                          const float* __restrict__ b18)
{
    const int n = blockIdx.x * blockDim.x + threadIdx.x;
    float s = 0.f;
    for (int k = 0; k < DIN; k++) s = fmaf(bi[k], W18[(size_t)k * DHID + n], s);
    g_bc[n] = s + b18[n];
}

__global__ void g2_kernel(const float* __restrict__ ac, const float* __restrict__ W12,
                          const float* __restrict__ b12)
{
    const int b = blockIdx.x;
    const int n = threadIdx.x;
    const float scale = rsqrtf((float)NPAIR);
    float s = 0.f;
    const float* arow = ac + (size_t)b * DIN;
    for (int k = 0; k < DIN; k++) s = fmaf(arow[k], W12[(size_t)k * DHID + n], s);
    g_g2[b * DHID + n] = s * scale + b12[n];
}

__global__ void wd_kernel(const float* __restrict__ W28, const float* __restrict__ Wo1)
{
    __shared__ float wrow[DOUT];
    const int m = blockIdx.x;
    const int n = threadIdx.x;
    wrow[n] = W28[(size_t)m * DOUT + n];
    __syncthreads();
    float s = 0.f;
    #pragma unroll 8
    for (int k = 0; k < DOUT; k++) s = fmaf(wrow[k], Wo1[(size_t)k * DOUT + n], s);
    g_Wd[m * DOUT + n] = s;
}

__global__ void bd_kernel(const float* __restrict__ b28, const float* __restrict__ Wo1,
                          const float* __restrict__ bo1)
{
    const int n = threadIdx.x;
    float s = 0.f;
    for (int k = 0; k < DOUT; k++) s = fmaf(b28[k], Wo1[(size_t)k * DOUT + n], s);
    g_bd[n] = s + bo1[n];
}

// ============================================================================
// Launch. Live inputs: cpe(0), ac(3), Wi(4), bi(5), W1(6), b1(7), W2(8),
// b2(9), Wo1(10), bo1(11), Wo2(12), bo2(13). he/hc dead.
// ============================================================================
extern "C" void kernel_launch(void* const* d_in, const int* in_sizes, int n_in,
                              void* d_out, int out_size)
{
    const float* cpe = (const float*)d_in[0];
    const float* ac  = (const float*)d_in[3];
    const float* Wi  = (const float*)d_in[4];
    const float* bi  = (const float*)d_in[5];
    const float* W1  = (const float*)d_in[6];
    const float* b1  = (const float*)d_in[7];
    const float* W2  = (const float*)d_in[8];
    const float* b2  = (const float*)d_in[9];
    const float* Wo1 = (const float*)d_in[10];
    const float* bo1 = (const float*)d_in[11];
    const float* Wo2 = (const float*)d_in[12];
    const float* bo2 = (const float*)d_in[13];
    float* out = (float*)d_out;

    float *pWc, *pHp;
    cudaGetSymbolAddress((void**)&pWc, g_Wc);
    cudaGetSymbolAddress((void**)&pHp, g_hp);

    const float* W18 = W1 + (size_t)8 * DIN * DHID;
    const float* b18 = b1 + 8 * DHID;
    const float* W12 = W1 + (size_t)2 * DIN * DHID;
    const float* b12 = b1 + 2 * DHID;
    const float* W28 = W2 + (size_t)8 * DHID * DOUT;
    const float* b28 = b2 + 8 * DOUT;

    // 1. Folded-weight precompute (Wc on tensor cores too).
    tf32gemm<0><<<dim3(DHID / 128, (DPAIR + 127) / 128), 256>>>(
        Wi, W18, pWc, DPAIR, DHID, DIN);
    bc_kernel<<<2, 256>>>(bi, W18, b18);
    g2_kernel<<<Bb, DHID>>>(ac, W12, b12);

    // 2. Main GEMM + fused h_p epilogue: [21568,1636] @ [1636,512] (tf32 MMA).
    tf32gemm<1><<<dim3(DHID / 128, (MROWS + 127) / 128), 256>>>(
        cpe, pWc, pHp, MROWS, DHID, DPAIR);

    // 3. Tail precompute + fused second GEMM + ReLU + Wo2 dot -> out.
    wd_kernel<<<DHID, DOUT>>>(W28, Wo1);
    bd_kernel<<<1, DOUT>>>(b28, Wo1, bo1);
    tail_kernel<<<MROWS / 64, 256>>>(Wo2, bo2, out);
}

// round 4
// speedup vs baseline: 3.4568x; 1.8436x over previous
#include <cuda_runtime.h>
#include <math.h>
#include <stdint.h>

#define Bb     32
#define NPAIR  674
#define DPAIR  1636
#define DIN    768
#define DHID   512
#define DOUT   256
#define MROWS  21568   // Bb * NPAIR

// ---- scratch (static device globals) ----
__device__ float g_Wc[DPAIR * DHID];          // tf32-rounded Wi @ W1[8]
__device__ float g_bc[DHID];
__device__ float g_g2[Bb * DHID];
__device__ float g_Wd[DHID * DOUT];           // tf32-rounded W2[8] @ Wo1
__device__ float g_bd[DOUT];
__device__ float g_hp[(size_t)MROWS * DHID];  // tf32-rounded h_p

__device__ __forceinline__ uint32_t f2tf32(float f) {
    uint32_t u;
    asm("cvt.rna.tf32.f32 %0, %1;" : "=r"(u) : "f"(f));
    return u;
}

__device__ __forceinline__ void mma_tf32(float* d, const uint32_t* a, const uint32_t* b) {
    asm volatile(
        "mma.sync.aligned.m16n8k8.row.col.f32.tf32.tf32.f32 "
        "{%0,%1,%2,%3}, {%4,%5,%6,%7}, {%8,%9}, {%0,%1,%2,%3};"
        : "+f"(d[0]), "+f"(d[1]), "+f"(d[2]), "+f"(d[3])
        : "r"(a[0]), "r"(a[1]), "r"(a[2]), "r"(a[3]), "r"(b[0]), "r"(b[1]));
}

__device__ __forceinline__ void cp16(uint32_t saddr, const void* gptr, bool valid) {
    int sz = valid ? 16 : 0;   // src-size 0 -> zero-fill destination
    asm volatile("cp.async.cg.shared.global [%0], [%1], 16, %2;"
                 :: "r"(saddr), "l"(gptr), "r"(sz));
}
__device__ __forceinline__ void cp_commit() { asm volatile("cp.async.commit_group;"); }
__device__ __forceinline__ void cp_wait1()  { asm volatile("cp.async.wait_group 1;"); }

// ============================================================================
// Pipelined TF32 MMA GEMM. Block tile (NWM*64) x BN, BK=32, 3-stage cp.async.
// Warp tile 64x32 via m16n8k8; warp grid NWM x NWN (NWN = NTHREADS/32/NWM).
// A row-major [M,K] (OOB rows/k zero-filled), B row-major [K,N], N % BN == 0.
// smem A[stage][BM][36] (bank 4m+k conflict-free), B[stage][32][BN+8]
// (bank 8k+n conflict-free). CVTA/CVTB: cvt operand to tf32 after LDS (skip
// when the source array is already tf32-rounded).
// EPI=0: C = round_tf32(A@B)
// EPI=1: C = round_tf32(relu((A@B + g_bc[n] + g_g2[row/674][n]) * 0.5))
// EPI=2: out[row] = dot(relu(A@B + g_bd), Wo2) + bo2   (C unused)
// ============================================================================
template<int NWM, int BN, int NTHREADS, int EPI, bool CVTA, bool CVTB>
__global__ __launch_bounds__(NTHREADS) void gemm_pipe(
    const float* __restrict__ A, const float* __restrict__ Bm,
    float* __restrict__ C, int M, int N, int K,
    const float* __restrict__ Wo2, const float* __restrict__ bo2,
    float* __restrict__ out)
{
    constexpr int BM   = NWM * 64;
    constexpr int NWN  = NTHREADS / 32 / NWM;
    constexpr int SA   = 36;
    constexpr int SB   = BN + 8;
    constexpr int ASTG = BM * SA;
    constexpr int BSTG = 32 * SB;

    extern __shared__ float dsm[];
    float* Asm = dsm;
    float* Bsm = dsm + 3 * ASTG;
    const uint32_t smb = (uint32_t)__cvta_generic_to_shared(dsm);

    const int tid  = threadIdx.x;
    const int lane = tid & 31;
    const int wid  = tid >> 5;
    const int wm   = wid / NWN;
    const int wn   = wid % NWN;
    const int m0   = blockIdx.y * BM;
    const int n0   = blockIdx.x * BN;
    const int q    = lane & 3;
    const int g    = lane >> 2;

    float acc[4][4][4];
    #pragma unroll
    for (int mt = 0; mt < 4; mt++)
        #pragma unroll
        for (int nt = 0; nt < 4; nt++)
            #pragma unroll
            for (int i = 0; i < 4; i++) acc[mt][nt][i] = 0.f;

    const int niter = (K + 31) >> 5;

    auto load_stage = [&](int s, int k0) {
        const uint32_t abase = smb + (uint32_t)(s * ASTG) * 4;
        for (int qx = tid; qx < BM * 8; qx += NTHREADS) {
            const int row  = qx >> 3;
            const int kseg = (qx & 7) * 4;
            const bool v = (m0 + row < M) && (k0 + kseg < K);
            cp16(abase + (uint32_t)(row * SA + kseg) * 4,
                 A + (size_t)(m0 + row) * K + k0 + kseg, v);
        }
        const uint32_t bbase = smb + (uint32_t)(3 * ASTG + s * BSTG) * 4;
        for (int qx = tid; qx < 32 * (BN / 4); qx += NTHREADS) {
            const int row  = qx / (BN / 4);
            const int nseg = (qx % (BN / 4)) * 4;
            const bool v = (k0 + row) < K;
            cp16(bbase + (uint32_t)(row * SB + nseg) * 4,
                 Bm + (size_t)(k0 + row) * N + n0 + nseg, v);
        }
    };

    load_stage(0, 0);
    cp_commit();
    load_stage(1, 32);
    cp_commit();

    for (int it = 0; it < niter; it++) {
        cp_wait1();
        __syncthreads();

        const int nxt = it + 2;
        if (nxt < niter) load_stage(nxt % 3, nxt * 32);
        cp_commit();

        const float* As = Asm + (it % 3) * ASTG;
        const float* Bs = Bsm + (it % 3) * BSTG;
        const int mb = wm * 64 + g;
        const int nb = wn * 32 + g;

        #pragma unroll
        for (int k8 = 0; k8 < 4; k8++) {
            const int kk = k8 * 8 + q;
            uint32_t af[4][4], bf[4][2];
            #pragma unroll
            for (int mt = 0; mt < 4; mt++) {
                const float* ar0 = As + (mb + mt * 16) * SA;
                const float* ar1 = As + (mb + mt * 16 + 8) * SA;
                float a0 = ar0[kk], a1 = ar1[kk], a2 = ar0[kk + 4], a3 = ar1[kk + 4];
                if (CVTA) {
                    af[mt][0] = f2tf32(a0); af[mt][1] = f2tf32(a1);
                    af[mt][2] = f2tf32(a2); af[mt][3] = f2tf32(a3);
                } else {
                    af[mt][0] = __float_as_uint(a0); af[mt][1] = __float_as_uint(a1);
                    af[mt][2] = __float_as_uint(a2); af[mt][3] = __float_as_uint(a3);
                }
            }
            #pragma unroll
            for (int nt = 0; nt < 4; nt++) {
                float b0 = Bs[kk * SB + nb + nt * 8];
                float b1 = Bs[(kk + 4) * SB + nb + nt * 8];
                if (CVTB) {
                    bf[nt][0] = f2tf32(b0); bf[nt][1] = f2tf32(b1);
                } else {
                    bf[nt][0] = __float_as_uint(b0); bf[nt][1] = __float_as_uint(b1);
                }
            }
            #pragma unroll
            for (int mt = 0; mt < 4; mt++)
                #pragma unroll
                for (int nt = 0; nt < 4; nt++)
                    mma_tf32(acc[mt][nt], af[mt], bf[nt]);
        }
        __syncthreads();
    }

    if (EPI == 0 || EPI == 1) {
        #pragma unroll
        for (int mt = 0; mt < 4; mt++) {
            #pragma unroll
            for (int half = 0; half < 2; half++) {
                const int r = m0 + wm * 64 + mt * 16 + g + half * 8;
                if (r >= M) continue;
                const float* g2r = (EPI == 1) ? (g_g2 + (r / NPAIR) * DHID) : nullptr;
                #pragma unroll
                for (int nt = 0; nt < 4; nt++) {
                    const int c = n0 + wn * 32 + nt * 8 + 2 * q;
                    float v0 = acc[mt][nt][half * 2 + 0];
                    float v1 = acc[mt][nt][half * 2 + 1];
                    if (EPI == 1) {
                        v0 = fmaxf((v0 + g_bc[c    ] + g2r[c    ]) * 0.5f, 0.f);
                        v1 = fmaxf((v1 + g_bc[c + 1] + g2r[c + 1]) * 0.5f, 0.f);
                    }
                    float2 w = make_float2(__uint_as_float(f2tf32(v0)),
                                           __uint_as_float(f2tf32(v1)));
                    *(float2*)(C + (size_t)r * N + c) = w;
                }
            }
        }
    } else {
        // EPI == 2: fused out[r] = dot(relu(acc + g_bd), Wo2) + bo2
        float bdv[4][2], wv[4][2];
        #pragma unroll
        for (int nt = 0; nt < 4; nt++)
            #pragma unroll
            for (int j = 0; j < 2; j++) {
                const int c = wn * 32 + nt * 8 + 2 * q + j;
                bdv[nt][j] = g_bd[c];
                wv[nt][j]  = Wo2[c];
            }
        float* red = dsm;   // [BM][NWN]; stage smem reusable (all cp groups drained)
        #pragma unroll
        for (int mt = 0; mt < 4; mt++) {
            #pragma unroll
            for (int half = 0; half < 2; half++) {
                float p = 0.f;
                #pragma unroll
                for (int nt = 0; nt < 4; nt++)
                    #pragma unroll
                    for (int j = 0; j < 2; j++) {
                        const float h = fmaxf(acc[mt][nt][half * 2 + j] + bdv[nt][j], 0.f);
                        p = fmaf(h, wv[nt][j], p);
                    }
                p += __shfl_xor_sync(0xffffffffu, p, 1);
                p += __shfl_xor_sync(0xffffffffu, p, 2);
                if (q == 0) {
                    const int rl = wm * 64 + mt * 16 + g + half * 8;
                    red[rl * NWN + wn] = p;
                }
            }
        }
        __syncthreads();
        if (tid < BM) {
            float s = bo2[0];
            #pragma unroll
            for (int w = 0; w < NWN; w++) s += red[tid * NWN + w];
            if (m0 + tid < M) out[m0 + tid] = s;
        }
    }
}

// ---- small precompute kernels ----
__global__ void bc_kernel(const float* __restrict__ bi, const float* __restrict__ W18,
                          const float* __restrict__ b18)
{
    const int n = blockIdx.x * blockDim.x + threadIdx.x;
    float s = 0.f;
    for (int k = 0; k < DIN; k++) s = fmaf(bi[k], W18[(size_t)k * DHID + n], s);
    g_bc[n] = s + b18[n];
}

__global__ void g2_kernel(const float* __restrict__ ac, const float* __restrict__ W12,
                          const float* __restrict__ b12)
{
    const int b = blockIdx.x;
    const int n = threadIdx.x;
    const float scale = rsqrtf((float)NPAIR);
    float s = 0.f;
    const float* arow = ac + (size_t)b * DIN;
    for (int k = 0; k < DIN; k++) s = fmaf(arow[k], W12[(size_t)k * DHID + n], s);
    g_g2[b * DHID + n] = s * scale + b12[n];
}

__global__ void wd_kernel(const float* __restrict__ W28, const float* __restrict__ Wo1)
{
    __shared__ float wrow[DOUT];
    const int m = blockIdx.x;
    const int n = threadIdx.x;
    wrow[n] = W28[(size_t)m * DOUT + n];
    __syncthreads();
    float s = 0.f;
    #pragma unroll 8
    for (int k = 0; k < DOUT; k++) s = fmaf(wrow[k], Wo1[(size_t)k * DOUT + n], s);
    g_Wd[m * DOUT + n] = __uint_as_float(f2tf32(s));   // pre-round to tf32
}

__global__ void bd_kernel(const float* __restrict__ b28, const float* __restrict__ Wo1,
                          const float* __restrict__ bo1)
{
    const int n = threadIdx.x;
    float s = 0.f;
    for (int k = 0; k < DOUT; k++) s = fmaf(b28[k], Wo1[(size_t)k * DOUT + n], s);
    g_bd[n] = s + bo1[n];
}

// ============================================================================
// Launch. Live inputs: cpe(0), ac(3), Wi(4), bi(5), W1(6), b1(7), W2(8),
// b2(9), Wo1(10), bo1(11), Wo2(12), bo2(13). he/hc dead.
// ============================================================================
extern "C" void kernel_launch(void* const* d_in, const int* in_sizes, int n_in,
                              void* d_out, int out_size)
{
    const float* cpe = (const float*)d_in[0];
    const float* ac  = (const float*)d_in[3];
    const float* Wi  = (const float*)d_in[4];
    const float* bi  = (const float*)d_in[5];
    const float* W1  = (const float*)d_in[6];
    const float* b1  = (const float*)d_in[7];
    const float* W2  = (const float*)d_in[8];
    const float* b2  = (const float*)d_in[9];
    const float* Wo1 = (const float*)d_in[10];
    const float* bo1 = (const float*)d_in[11];
    const float* Wo2 = (const float*)d_in[12];
    const float* bo2 = (const float*)d_in[13];
    float* out = (float*)d_out;

    float *pWc, *pHp, *pWd;
    cudaGetSymbolAddress((void**)&pWc, g_Wc);
    cudaGetSymbolAddress((void**)&pHp, g_hp);
    cudaGetSymbolAddress((void**)&pWd, g_Wd);

    const float* W18 = W1 + (size_t)8 * DIN * DHID;
    const float* b18 = b1 + 8 * DHID;
    const float* W12 = W1 + (size_t)2 * DIN * DHID;
    const float* b12 = b1 + 2 * DHID;
    const float* W28 = W2 + (size_t)8 * DHID * DOUT;
    const float* b28 = b2 + 8 * DOUT;

    // dynamic smem: 3 stages of A[BM][36] + B[32][BN+8]
    constexpr int SM_MAIN = 3 * (128 * 36 + 32 * 136) * 4;   // 107520
    constexpr int SM_TAIL = 3 * (64 * 36 + 32 * 264) * 4;    // 129024

    auto kWc   = gemm_pipe<2, 128, 256, 0, true,  true >;
    auto kMain = gemm_pipe<2, 128, 256, 1, true,  false>;
    auto kTail = gemm_pipe<1, 256, 256, 2, false, false>;
    cudaFuncSetAttribute(kWc,   cudaFuncAttributeMaxDynamicSharedMemorySize, SM_MAIN);
    cudaFuncSetAttribute(kMain, cudaFuncAttributeMaxDynamicSharedMemorySize, SM_MAIN);
    cudaFuncSetAttribute(kTail, cudaFuncAttributeMaxDynamicSharedMemorySize, SM_TAIL);

    // 1. Folded weights: Wc = Wi @ W18 (tf32-rounded), bc, g2, Wd, bd.
    kWc<<<dim3(DHID / 128, (DPAIR + 127) / 128), 256, SM_MAIN>>>(
        Wi, W18, pWc, DPAIR, DHID, DIN, nullptr, nullptr, nullptr);
    bc_kernel<<<2, 256>>>(bi, W18, b18);
    g2_kernel<<<Bb, DHID>>>(ac, W12, b12);
    wd_kernel<<<DHID, DOUT>>>(W28, Wo1);
    bd_kernel<<<1, DOUT>>>(b28, Wo1, bo1);

    // 2. Main GEMM + h_p epilogue: [21568,1636] @ [1636,512].
    kMain<<<dim3(DHID / 128, (MROWS + 127) / 128), 256, SM_MAIN>>>(
        cpe, pWc, pHp, MROWS, DHID, DPAIR, nullptr, nullptr, nullptr);

    // 3. Fused tail: out = relu(h_p @ Wd + bd) . Wo2 + bo2  (hid never in gmem).
    kTail<<<dim3(1, MROWS / 64), 256, SM_TAIL>>>(
        pHp, pWd, nullptr, MROWS, DOUT, DHID, Wo2, bo2, out);
}

// round 8
// speedup vs baseline: 4.1379x; 1.1970x over previous
#include <cuda_runtime.h>
#include <cuda_fp16.h>
#include <stdint.h>

#define Bb        32
#define NPAIR     674
#define DPAIR     1636
#define DPAIR_PAD 1640   // fp16 row stride: 1640*2 = 3280 B, 16B-aligned for cp.async
#define DIN       768
#define DHID      512
#define DOUT      256
#define MROWS     21568  // Bb * NPAIR

// ---- scratch (static device globals) ----
__device__ __half g_cpeh[(size_t)MROWS * DPAIR_PAD];   // fp16 cpe, padded stride
__device__ __half g_Wih[DPAIR * DIN];                  // fp16 Wi
__device__ __half g_W18h[DIN * DHID];                  // fp16 W1[8]
__device__ __half g_Wch[DPAIR * DHID];                 // fp16 Wi @ W1[8]
__device__ __half g_Wdh[DHID * DOUT];                  // fp16 W2[8] @ Wo1
__device__ __half g_hph[(size_t)MROWS * DHID];         // fp16 h_p
__device__ float  g_bc[DHID];
__device__ float  g_g2[Bb * DHID];
__device__ float  g_bd[DOUT];

__device__ __forceinline__ void cp16(uint32_t saddr, const void* gptr, bool valid) {
    int sz = valid ? 16 : 0;   // src-size 0 -> zero-fill, no global read
    asm volatile("cp.async.cg.shared.global [%0], [%1], 16, %2;"
                 :: "r"(saddr), "l"(gptr), "r"(sz));
}
__device__ __forceinline__ void cp_commit() { asm volatile("cp.async.commit_group;"); }
__device__ __forceinline__ void cp_wait1()  { asm volatile("cp.async.wait_group 1;"); }

__device__ __forceinline__ void ldsm_x4(uint32_t* r, uint32_t addr) {
    asm volatile("ldmatrix.sync.aligned.m8n8.x4.shared.b16 {%0,%1,%2,%3}, [%4];"
                 : "=r"(r[0]), "=r"(r[1]), "=r"(r[2]), "=r"(r[3]) : "r"(addr));
}
__device__ __forceinline__ void ldsm_x4_t(uint32_t* r, uint32_t addr) {
    asm volatile("ldmatrix.sync.aligned.m8n8.x4.trans.shared.b16 {%0,%1,%2,%3}, [%4];"
                 : "=r"(r[0]), "=r"(r[1]), "=r"(r[2]), "=r"(r[3]) : "r"(addr));
}
__device__ __forceinline__ void mma_f16(float* d, const uint32_t* a, const uint32_t* b) {
    asm volatile(
        "mma.sync.aligned.m16n8k16.row.col.f32.f16.f16.f32 "
        "{%0,%1,%2,%3}, {%4,%5,%6,%7}, {%8,%9}, {%0,%1,%2,%3};"
        : "+f"(d[0]), "+f"(d[1]), "+f"(d[2]), "+f"(d[3])
        : "r"(a[0]), "r"(a[1]), "r"(a[2]), "r"(a[3]), "r"(b[0]), "r"(b[1]));
}

// ============================================================================
// Pipelined FP16 MMA GEMM (fp32 accumulate). Block tile (NWM*64) x BN, BK=32,
// 3-stage cp.async, ldmatrix fragment loads. Warp tile 64x32 via m16n8k16.
// A row-major [M,K] fp16 with row stride lda (lda*2 must be 16B-aligned),
// B row-major [K,N] fp16 (N % BN == 0, N*2 16B-aligned).
// smem A[stage][BM][40], B[stage][32][BN+8] (both strides multiple of 16B).
// OOB: A rows m>=M zero-filled; B k-rows >= K zero-filled, so any pad garbage
// in A's k-straddle multiplies zero.
// EPI=0: C = half(A@B)
// EPI=1: C = half(relu((A@B + g_bc[n] + g_g2[row/674][n]) * 0.5))
// EPI=2: out[row] = dot(relu(A@B + g_bd), Wo2) + bo2   (C unused)
// ============================================================================
template<int NWM, int BN, int NTHREADS, int EPI>
__global__ __launch_bounds__(NTHREADS) void hgemm(
    const __half* __restrict__ A, int lda, const __half* __restrict__ Bm,
    __half* __restrict__ C, int M, int N, int K,
    const float* __restrict__ Wo2, const float* __restrict__ bo2,
    float* __restrict__ out)
{
    constexpr int BM   = NWM * 64;
    constexpr int NWN  = NTHREADS / 32 / NWM;
    constexpr int SA   = 40;        // halves per A smem row (80 B, mult of 16)
    constexpr int SB   = BN + 8;    // halves per B smem row
    constexpr int ASTG = BM * SA;
    constexpr int BSTG = 32 * SB;

    extern __shared__ char smraw[];
    const uint32_t smb  = (uint32_t)__cvta_generic_to_shared(smraw);
    const uint32_t bsmb = smb + 3 * ASTG * 2;

    const int tid  = threadIdx.x;
    const int lane = tid & 31;
    const int wid  = tid >> 5;
    const int wm   = wid / NWN;
    const int wn   = wid % NWN;
    const int m0   = blockIdx.y * BM;
    const int n0   = blockIdx.x * BN;
    const int q    = lane & 3;
    const int g    = lane >> 2;

    float acc[4][4][4];
    #pragma unroll
    for (int mt = 0; mt < 4; mt++)
        #pragma unroll
        for (int nt = 0; nt < 4; nt++)
            #pragma unroll
            for (int i = 0; i < 4; i++) acc[mt][nt][i] = 0.f;

    const int niter = (K + 31) >> 5;

    auto load_stage = [&](int s, int k0) {
        const uint32_t abase = smb + (uint32_t)(s * ASTG) * 2;
        for (int qx = tid; qx < BM * 4; qx += NTHREADS) {
            const int row  = qx >> 2;
            const int kseg = (qx & 3) * 8;
            const bool v = (m0 + row < M) && (k0 + kseg < K);
            cp16(abase + (uint32_t)(row * SA + kseg) * 2,
                 A + (size_t)(m0 + row) * lda + k0 + kseg, v);
        }
        const uint32_t bbase = bsmb + (uint32_t)(s * BSTG) * 2;
        for (int qx = tid; qx < 32 * (BN / 8); qx += NTHREADS) {
            const int row  = qx / (BN / 8);
            const int nseg = (qx % (BN / 8)) * 8;
            const bool v = (k0 + row) < K;
            cp16(bbase + (uint32_t)(row * SB + nseg) * 2,
                 Bm + (size_t)(k0 + row) * N + n0 + nseg, v);
        }
    };

    load_stage(0, 0);
    cp_commit();
    load_stage(1, 32);
    cp_commit();

    const uint32_t a_ld0 = smb +
        (uint32_t)((wm * 64 + (lane & 15)) * SA + (lane >> 4) * 8) * 2;
    const uint32_t b_ld0 = bsmb +
        (uint32_t)(((lane & 7) + ((lane >> 3) & 1) * 8) * SB
                   + wn * 32 + (lane >> 4) * 8) * 2;

    for (int it = 0; it < niter; it++) {
        cp_wait1();
        __syncthreads();

        const int nxt = it + 2;
        if (nxt < niter) load_stage(nxt % 3, nxt * 32);
        cp_commit();

        const uint32_t ast = (uint32_t)((it % 3) * ASTG) * 2;
        const uint32_t bst = (uint32_t)((it % 3) * BSTG) * 2;

        #pragma unroll
        for (int k16 = 0; k16 < 2; k16++) {
            uint32_t af[4][4], bf[2][4];
            const uint32_t aaddr = a_ld0 + ast + (uint32_t)(k16 * 16) * 2;
            #pragma unroll
            for (int mt = 0; mt < 4; mt++)
                ldsm_x4(af[mt], aaddr + (uint32_t)(mt * 16 * SA) * 2);
            const uint32_t baddr = b_ld0 + bst + (uint32_t)(k16 * 16 * SB) * 2;
            #pragma unroll
            for (int np = 0; np < 2; np++)
                ldsm_x4_t(bf[np], baddr + (uint32_t)(np * 16) * 2);
            #pragma unroll
            for (int mt = 0; mt < 4; mt++)
                #pragma unroll
                for (int nt = 0; nt < 4; nt++)
                    mma_f16(acc[mt][nt], af[mt], &bf[nt >> 1][(nt & 1) * 2]);
        }
        __syncthreads();
    }

    if (EPI == 0 || EPI == 1) {
        #pragma unroll
        for (int mt = 0; mt < 4; mt++) {
            #pragma unroll
            for (int half = 0; half < 2; half++) {
                const int r = m0 + wm * 64 + mt * 16 + g + half * 8;
                if (r >= M) continue;
                const float* g2r = (EPI == 1) ? (g_g2 + (r / NPAIR) * DHID) : nullptr;
                #pragma unroll
                for (int nt = 0; nt < 4; nt++) {
                    const int c = n0 + wn * 32 + nt * 8 + 2 * q;
                    float v0 = acc[mt][nt][half * 2 + 0];
                    float v1 = acc[mt][nt][half * 2 + 1];
                    if (EPI == 1) {
                        v0 = fmaxf((v0 + g_bc[c    ] + g2r[c    ]) * 0.5f, 0.f);
                        v1 = fmaxf((v1 + g_bc[c + 1] + g2r[c + 1]) * 0.5f, 0.f);
                    }
                    *(__half2*)(C + (size_t)r * N + c) = __floats2half2_rn(v0, v1);
                }
            }
        }
    } else {
        // EPI == 2: fused out[r] = dot(relu(acc + g_bd), Wo2) + bo2
        float bdv[4][2], wv[4][2];
        #pragma unroll
        for (int nt = 0; nt < 4; nt++)
            #pragma unroll
            for (int j = 0; j < 2; j++) {
                const int c = wn * 32 + nt * 8 + 2 * q + j;
                bdv[nt][j] = g_bd[c];
                wv[nt][j]  = Wo2[c];
            }
        float* red = (float*)smraw;   // [BM][NWN]; all cp groups drained
        #pragma unroll
        for (int mt = 0; mt < 4; mt++) {
            #pragma unroll
            for (int half = 0; half < 2; half++) {
                float p = 0.f;
                #pragma unroll
                for (int nt = 0; nt < 4; nt++)
                    #pragma unroll
                    for (int j = 0; j < 2; j++) {
                        const float h = fmaxf(acc[mt][nt][half * 2 + j] + bdv[nt][j], 0.f);
                        p = fmaf(h, wv[nt][j], p);
                    }
                p += __shfl_xor_sync(0xffffffffu, p, 1);
                p += __shfl_xor_sync(0xffffffffu, p, 2);
                if (q == 0) {
                    const int rl = wm * 64 + mt * 16 + g + half * 8;
                    red[rl * NWN + wn] = p;
                }
            }
        }
        __syncthreads();
        if (tid < BM) {
            float s = bo2[0];
            #pragma unroll
            for (int w = 0; w < NWN; w++) s += red[tid * NWN + w];
            if (m0 + tid < M) out[m0 + tid] = s;
        }
    }
}

// ---- fp32 -> fp16 bulk convert, contiguous (stride preserved) ----
__global__ void cvt_kernel(const float* __restrict__ in, __half* __restrict__ out, int n2)
{
    const float2* i2 = (const float2*)in;
    __half2* o2 = (__half2*)out;
    for (int i = blockIdx.x * blockDim.x + threadIdx.x; i < n2;
         i += gridDim.x * blockDim.x)
        o2[i] = __float22half2_rn(i2[i]);
}

// ---- cpe fp32 [MROWS x DPAIR] -> fp16 padded [MROWS x DPAIR_PAD], pad zeroed ----
__global__ void cvt_cpe_kernel(const float* __restrict__ in, __half* __restrict__ out)
{
    const int nseg = DPAIR / 4;   // 409 float4 segs per row
    for (int idx = blockIdx.x * blockDim.x + threadIdx.x; idx < MROWS * nseg;
         idx += gridDim.x * blockDim.x) {
        const int row = idx / nseg;
        const int c4  = (idx % nseg) * 4;
        float4 v = *(const float4*)(in + (size_t)row * DPAIR + c4);
        __half2* dst = (__half2*)(out + (size_t)row * DPAIR_PAD + c4);
        dst[0] = __floats2half2_rn(v.x, v.y);
        dst[1] = __floats2half2_rn(v.z, v.w);
        if (c4 == 0) {   // zero the 4 pad halves of this row
            __half2* pad = (__half2*)(out + (size_t)row * DPAIR_PAD + DPAIR);
            pad[0] = __half2half2(__float2half(0.f));
            pad[1] = __half2half2(__float2half(0.f));
        }
    }
}

// ---- small precompute kernels ----
__global__ void bc_kernel(const float* __restrict__ bi, const float* __restrict__ W18,
                          const float* __restrict__ b18)
{
    const int n = blockIdx.x * blockDim.x + threadIdx.x;
    float s = 0.f;
    for (int k = 0; k < DIN; k++) s = fmaf(bi[k], W18[(size_t)k * DHID + n], s);
    g_bc[n] = s + b18[n];
}

__global__ void g2_kernel(const float* __restrict__ ac, const float* __restrict__ W12,
                          const float* __restrict__ b12)
{
    const int b = blockIdx.x;
    const int n = threadIdx.x;
    const float scale = rsqrtf((float)NPAIR);
    float s = 0.f;
    const float* arow = ac + (size_t)b * DIN;
    for (int k = 0; k < DIN; k++) s = fmaf(arow[k], W12[(size_t)k * DHID + n], s);
    g_g2[b * DHID + n] = s * scale + b12[n];
}

// Wd = W2[8] @ Wo1 -> fp16. 16 m-rows per block via smem tile, Wo1 coalesced.
__global__ __launch_bounds__(256) void wd_kernel(const float* __restrict__ W28,
                                                 const float* __restrict__ Wo1)
{
    __shared__ float w28s[16][DOUT];
    const int m0 = blockIdx.x * 16;
    const int n  = threadIdx.x;
    for (int i = threadIdx.x; i < 16 * DOUT; i += 256)
        w28s[i >> 8][i & 255] = W28[(size_t)(m0 + (i >> 8)) * DOUT + (i & 255)];
    __syncthreads();
    float acc[16];
    #pragma unroll
    for (int mm = 0; mm < 16; mm++) acc[mm] = 0.f;
    for (int k = 0; k < DOUT; k++) {
        const float w = Wo1[(size_t)k * DOUT + n];
        #pragma unroll
        for (int mm = 0; mm < 16; mm++) acc[mm] = fmaf(w28s[mm][k], w, acc[mm]);
    }
    #pragma unroll
    for (int mm = 0; mm < 16; mm++)
        g_Wdh[(size_t)(m0 + mm) * DOUT + n] = __float2half_rn(acc[mm]);
}

__global__ void bd_kernel(const float* __restrict__ b28, const float* __restrict__ Wo1,
                          const float* __restrict__ bo1)
{
    const int n = threadIdx.x;
    float s = 0.f;
    for (int k = 0; k < DOUT; k++) s = fmaf(b28[k], Wo1[(size_t)k * DOUT + n], s);
    g_bd[n] = s + bo1[n];
}

// ============================================================================
// Launch. Live inputs: cpe(0), ac(3), Wi(4), bi(5), W1(6), b1(7), W2(8),
// b2(9), Wo1(10), bo1(11), Wo2(12), bo2(13). he/hc dead.
// ============================================================================
extern "C" void kernel_launch(void* const* d_in, const int* in_sizes, int n_in,
                              void* d_out, int out_size)
{
    const float* cpe = (const float*)d_in[0];
    const float* ac  = (const float*)d_in[3];
    const float* Wi  = (const float*)d_in[4];
    const float* bi  = (const float*)d_in[5];
    const float* W1  = (const float*)d_in[6];
    const float* b1  = (const float*)d_in[7];
    const float* W2  = (const float*)d_in[8];
    const float* b2  = (const float*)d_in[9];
    const float* Wo1 = (const float*)d_in[10];
    const float* bo1 = (const float*)d_in[11];
    const float* Wo2 = (const float*)d_in[12];
    const float* bo2 = (const float*)d_in[13];
    float* out = (float*)d_out;

    __half *pCpeh, *pWih, *pW18h, *pWch, *pWdh, *pHph;
    cudaGetSymbolAddress((void**)&pCpeh, g_cpeh);
    cudaGetSymbolAddress((void**)&pWih,  g_Wih);
    cudaGetSymbolAddress((void**)&pW18h, g_W18h);
    cudaGetSymbolAddress((void**)&pWch,  g_Wch);
    cudaGetSymbolAddress((void**)&pWdh,  g_Wdh);
    cudaGetSymbolAddress((void**)&pHph,  g_hph);

    const float* W18 = W1 + (size_t)8 * DIN * DHID;
    const float* b18 = b1 + 8 * DHID;
    const float* W12 = W1 + (size_t)2 * DIN * DHID;
    const float* b12 = b1 + 2 * DHID;
    const float* W28 = W2 + (size_t)8 * DHID * DOUT;
    const float* b28 = b2 + 8 * DOUT;

    constexpr int SM_MAIN = 3 * (128 * 40 + 32 * 136) * 2;   // 56832 B
    constexpr int SM_TAIL = 3 * (64 * 40 + 32 * 264) * 2;    // 66048 B

    auto kWc   = hgemm<2, 128, 256, 0>;
    auto kMain = hgemm<2, 128, 256, 1>;
    auto kTail = hgemm<1, 256, 256, 2>;
    cudaFuncSetAttribute(kWc,   cudaFuncAttributeMaxDynamicSharedMemorySize, SM_MAIN);
    cudaFuncSetAttribute(kMain, cudaFuncAttributeMaxDynamicSharedMemorySize, SM_MAIN);
    cudaFuncSetAttribute(kTail, cudaFuncAttributeMaxDynamicSharedMemorySize, SM_TAIL);

    // 1. fp32 -> fp16 conversions (cpe into 16B-aligned padded layout)
    cvt_cpe_kernel<<<8192, 256>>>(cpe, pCpeh);
    cvt_kernel<<<(DPAIR * DIN / 2 + 255) / 256, 256>>>(Wi, pWih, DPAIR * DIN / 2);
    cvt_kernel<<<(DIN * DHID / 2 + 255) / 256, 256>>>(W18, pW18h, DIN * DHID / 2);

    // 2. Folded weights: Wc = Wi @ W18 (fp16), bc, g2, Wd, bd.
    kWc<<<dim3(DHID / 128, (DPAIR + 127) / 128), 256, SM_MAIN>>>(
        pWih, DIN, pW18h, pWch, DPAIR, DHID, DIN, nullptr, nullptr, nullptr);
    bc_kernel<<<2, 256>>>(bi, W18, b18);
    g2_kernel<<<Bb, DHID>>>(ac, W12, b12);
    wd_kernel<<<DHID / 16, 256>>>(W28, Wo1);
    bd_kernel<<<1, DOUT>>>(b28, Wo1, bo1);

    // 3. Main GEMM + h_p epilogue: [21568,1636] @ [1636,512] (fp16 MMA).
    kMain<<<dim3(DHID / 128, (MROWS + 127) / 128), 256, SM_MAIN>>>(
        pCpeh, DPAIR_PAD, pWch, pHph, MROWS, DHID, DPAIR, nullptr, nullptr, nullptr);

    // 4. Fused tail: out = relu(h_p @ Wd + bd) . Wo2 + bo2  (hid never in gmem).
    kTail<<<dim3(1, MROWS / 64), 256, SM_TAIL>>>(
        pHph, DHID, pWdh, nullptr, MROWS, DOUT, DHID, Wo2, bo2, out);
}